// round 12
// baseline (speedup 1.0000x reference)
#include <cuda_runtime.h>
#include <cstdint>

#define BB 8
#define CC 16
#define NND 512
#define EE 1024
#define PLANE (NND * NND)              // 262144
#define NPOS (BB * PLANE)              // 2,097,152
#define TPOS 512                       // positions per tile
#define TILES_PER_PLANE (PLANE / TPOS) // 512
#define TOTAL_TILES (NPOS / TPOS)      // 4096
#define G 444                          // persistent CTAs = 3 per SM
#define STAGES 2
#define STAGE_BYTES (TPOS * CC * 4)    // 32768
#define THREADS 256

// Shared memory layout (dynamic)
#define SM_ADJ   0                                   // 2 x 32768 = 65536
#define SM_LAB   (STAGES * STAGE_BYTES)              // 65536  (int[512] = 2048)
#define SM_MBAR  (SM_LAB + 2048)                     // 67584  (2 x 8)
#define SM_FLAGS (SM_MBAR + 16)                      // 67600  (int[2])
#define SM_ACCS  (SM_FLAGS + 8)                      // 67608  (float[8])
#define SM_ACCC  (SM_ACCS + 32)                      // 67640  (float[8])
#define SM_BAT   (SM_ACCC + 32)                      // 67672  (double[8], 8B aligned)
#define SM_TOTAL (SM_BAT + 64)                       // 67736

// Globals: overwrite-only partials + monotonic done counter (never zeroed;
// same inputs -> same values every call; last-CTA election via mod G).
__device__ float2 g_part[G * BB];
__device__ unsigned int g_done;

__device__ __forceinline__ uint32_t smem_u32(const void* p) {
    uint32_t a;
    asm("{ .reg .u64 t; cvta.to.shared.u64 t, %1; cvt.u32.u64 %0, t; }"
        : "=r"(a) : "l"(p));
    return a;
}

__device__ __forceinline__ void mbar_wait(uint32_t mbar, uint32_t parity) {
    asm volatile(
        "{\n\t"
        ".reg .pred P;\n\t"
        "LAB_WAIT_%=:\n\t"
        "mbarrier.try_wait.parity.acquire.cta.shared::cta.b64 P, [%0], %1, 0x989680;\n\t"
        "@P bra.uni LAB_DONE_%=;\n\t"
        "bra.uni LAB_WAIT_%=;\n\t"
        "LAB_DONE_%=:\n\t"
        "}"
        :: "r"(mbar), "r"(parity) : "memory");
}

// Fill stage `st` with tile `tl`: expect_tx + 16 class copies of 2KB each.
#define ISSUE_FILL(st, tl) do {                                                   \
    uint32_t _mb = mbar_base + (st) * 8;                                          \
    asm volatile("mbarrier.arrive.expect_tx.shared.b64 _, [%0], %1;"              \
                 :: "r"(_mb), "r"(STAGE_BYTES) : "memory");                       \
    const float* _src = adj + (size_t)((tl) >> 9) * (CC * PLANE)                  \
                            + (((tl) & (TILES_PER_PLANE - 1)) << 9);              \
    uint32_t _dst = smem_base + SM_ADJ + (st) * STAGE_BYTES;                      \
    _Pragma("unroll")                                                             \
    for (int _c = 0; _c < CC; _c++) {                                             \
        asm volatile(                                                             \
            "cp.async.bulk.shared::cluster.global.mbarrier::complete_tx::bytes "  \
            "[%0], [%1], %2, [%3];"                                               \
            :: "r"(_dst + _c * (TPOS * 4)), "l"(_src + (size_t)_c * PLANE),       \
               "r"(TPOS * 4), "r"(_mb) : "memory");                               \
    }                                                                             \
} while (0)

// ---------------------------------------------------------------------------
// Persistent fused kernel: 2-stage double-buffered bulk-async over 32KB tiles
// (512 positions x 16 classes); per-tile smem edge scatter; masked CE from
// smem; overwrite-only partials + last-CTA final reduction.
// ---------------------------------------------------------------------------
__global__ void __launch_bounds__(THREADS) fused_kernel(
    const float* __restrict__ adj, const unsigned char* __restrict__ mask,
    const int* __restrict__ ei, const int* __restrict__ ea,
    float* __restrict__ out) {

    extern __shared__ char smem[];
    int*    s_lab   = (int*)(smem + SM_LAB);
    int*    s_flags = (int*)(smem + SM_FLAGS);
    float*  s_accs  = (float*)(smem + SM_ACCS);
    float*  s_accc  = (float*)(smem + SM_ACCC);
    double* s_bat   = (double*)(smem + SM_BAT);
    const uint32_t smem_base = smem_u32(smem);
    const uint32_t mbar_base = smem_base + SM_MBAR;

    const int tid  = threadIdx.x;
    const int bid  = blockIdx.x;
    const int lane = tid & 31;
    const int w    = tid >> 5;

    // ---- one-time init: barriers, flags, per-batch accumulators
    if (tid == 0) {
#pragma unroll
        for (int s = 0; s < STAGES; s++)
            asm volatile("mbarrier.init.shared.b64 [%0], %1;"
                         :: "r"(mbar_base + s * 8), "r"(1) : "memory");
        asm volatile("fence.proxy.async.shared::cta;" ::: "memory");
    }
    if (tid < 2) s_flags[tid] = 0;
    if (tid < BB) { s_accs[tid] = 0.f; s_accc[tid] = 0.f; }
    __syncthreads();

    // ---- mask dtype detection from mask[0..1024) bytes
    //   u8 bool: nonzero at off%4==1; f32 1.0f: only %4==2,3; i32: only %4==0
    {
        uchar4 mv = ((const uchar4*)mask)[tid];
        if (mv.y) atomicOr(&s_flags[0], 1);
        if (mv.z | mv.w) atomicOr(&s_flags[1], 1);
    }

    // ---- prologue: fill both stages
    if (tid == 0) {
        ISSUE_FILL(0, bid);
        if (bid + G < TOTAL_TILES) ISSUE_FILL(1, bid + G);
    }
    __syncthreads();
    const int mode = s_flags[0] ? 0 : (s_flags[1] ? 2 : 1);

    // ---- main double-buffered loop
    int st = 0, ph = 0;
    for (int t = bid; t < TOTAL_TILES; t += G) {
        const int b = t >> 9;                            // 512 tiles per batch
        const int r = (t & (TILES_PER_PLANE - 1)) << 9;  // offset in plane

        // zero label tile (512 ints, 2 per thread)
        ((int2*)s_lab)[tid] = make_int2(0, 0);
        __syncthreads();

        // scatter this batch's edges (highest e wins, deterministic; L1-hot)
        const int base = b << 10;
#pragma unroll
        for (int k = 0; k < 4; k++) {
            int e = tid + (k << 8);
            int2 ij = ((const int2*)ei)[base + e];
            int a   = ea[base + e];
            int pos = ij.x * NND + ij.y - r;
            if ((unsigned)pos < (unsigned)TPOS)
                atomicMax(&s_lab[pos], (e << 5) | a);
        }

        // mask for my 2 positions (overlaps scatter & TMA fill)
        const int p = b * PLANE + r + tid * 2;
        float v0, v1;
        if (mode == 0) {
            uchar2 mm = ((const uchar2*)mask)[p >> 1];
            v0 = mm.x ? 1.f : 0.f; v1 = mm.y ? 1.f : 0.f;
        } else if (mode == 1) {
            int2 mm = ((const int2*)mask)[p >> 1];
            v0 = mm.x ? 1.f : 0.f; v1 = mm.y ? 1.f : 0.f;
        } else {
            float2 mm = ((const float2*)mask)[p >> 1];
            v0 = (mm.x != 0.f) ? 1.f : 0.f; v1 = (mm.y != 0.f) ? 1.f : 0.f;
        }

        __syncthreads();                     // labels ready
        int2 lv = ((const int2*)s_lab)[tid];
        const int lab0 = lv.x & 31, lab1 = lv.y & 31;

        // wait for this stage's adj tile
        mbar_wait(mbar_base + st * 8, ph);

        // CE from smem (conflict-free float2 LDS)
        const float* sa = (const float*)(smem + SM_ADJ + st * STAGE_BYTES);
        float sx = 0.f, sy = 0.f, p0 = 0.f, p1 = 0.f;
#pragma unroll
        for (int c = 0; c < CC; c++) {
            float2 x = ((const float2*)(sa + c * TPOS))[tid];
            sx += __expf(x.x);
            sy += __expf(x.y);
            p0 = (c == lab0) ? x.x : p0;
            p1 = (c == lab1) ? x.y : p1;
        }
        float lsum = v0 * (__logf(sx) - p0) + v1 * (__logf(sy) - p1);
        float lcnt = v0 + v1;

        // warp reduce -> per-batch smem accumulators
#pragma unroll
        for (int off = 16; off > 0; off >>= 1) {
            lsum += __shfl_down_sync(0xFFFFFFFFu, lsum, off);
            lcnt += __shfl_down_sync(0xFFFFFFFFu, lcnt, off);
        }
        if (lane == 0) {
            atomicAdd(&s_accs[b], lsum);
            atomicAdd(&s_accc[b], lcnt);
        }

        __syncthreads();                     // stage + s_lab fully consumed

        // refill this stage with the tile 2 steps ahead
        int tn = t + STAGES * G;
        if (tid == 0 && tn < TOTAL_TILES) ISSUE_FILL(st, tn);

        if (++st == STAGES) { st = 0; ph ^= 1; }
    }

    // ---- publish per-CTA partials, elect last CTA
    __syncthreads();
    if (tid < BB)
        g_part[bid * BB + tid] = make_float2(s_accs[tid], s_accc[tid]);
    __threadfence();
    __syncthreads();
    if (tid == 0) {
        unsigned int old = atomicAdd(&g_done, 1u);
        s_flags[0] = ((old % (unsigned)G) == (unsigned)(G - 1)) ? 2 : 3;
    }
    __syncthreads();

    // ---- last CTA: final reduction (warp w handles batch w)
    if (s_flags[0] == 2) {
        __threadfence();
        double ds = 0.0, dc = 0.0;
        for (int i = lane; i < G; i += 32) {
            float2 pr = __ldcg(&g_part[i * BB + w]);
            ds += (double)pr.x;
            dc += (double)pr.y;
        }
#pragma unroll
        for (int off = 16; off > 0; off >>= 1) {
            ds += __shfl_down_sync(0xFFFFFFFFu, ds, off);
            dc += __shfl_down_sync(0xFFFFFFFFu, dc, off);
        }
        if (lane == 0) {
            if (dc < 1.0) dc = 1.0;
            s_bat[w] = ds / dc;
        }
        __syncthreads();
        if (tid == 0) {
            double acc = 0.0;
#pragma unroll
            for (int i = 0; i < BB; i++) acc += s_bat[i];
            out[0] = (float)(acc / (double)BB);
        }
    }
}

// ---------------------------------------------------------------------------
extern "C" void kernel_launch(void* const* d_in, const int* in_sizes, int n_in,
                              void* d_out, int out_size) {
    const float*         adj  = (const float*)d_in[0];
    const unsigned char* mask = (const unsigned char*)d_in[1];
    const int*           ei   = (const int*)d_in[2];
    const int*           ea   = (const int*)d_in[3];

    cudaFuncSetAttribute(fused_kernel,
                         cudaFuncAttributeMaxDynamicSharedMemorySize, SM_TOTAL);
    fused_kernel<<<G, THREADS, SM_TOTAL>>>(adj, mask, ei, ea, (float*)d_out);
}

// round 16
// speedup vs baseline: 1.2425x; 1.2425x over previous
#include <cuda_runtime.h>
#include <cstdint>

#define BB 8
#define CC 16
#define NND 512
#define EE 1024
#define PLANE (NND * NND)            // 262144
#define NPOS (BB * PLANE)            // 2,097,152
#define CHUNK 2048                   // positions per CTA (two 1024 halves)
#define NCTA (NPOS / CHUNK)          // 1024
#define THREADS 256

// Globals: overwrite-only partials + monotonic done counter (never zeroed;
// same inputs -> same values every call; last-CTA election via mod NCTA).
__device__ float2 g_part[NCTA];
__device__ unsigned int g_done;

// ---------------------------------------------------------------------------
// One fused kernel, direct-LDG streaming (the proven-fastest structure).
// Each CTA: one edge scatter into a 2048-slot smem label tile, then two
// sequential 1024-position halves; during half 0 it L2-prefetches half 1.
// ---------------------------------------------------------------------------
__global__ void __launch_bounds__(THREADS, 4) fused_kernel(
    const float* __restrict__ adj, const unsigned char* __restrict__ mask,
    const int* __restrict__ ei, const int* __restrict__ ea,
    float* __restrict__ out) {

    __shared__ int    s_lab[CHUNK];        // 8KB
    __shared__ int    s_flags[2];
    __shared__ float  s_wred[16];          // wsum[8], wcnt[8]
    __shared__ double s_bat[BB];
    __shared__ int    s_role;

    const int tid  = threadIdx.x;
    const int bid  = blockIdx.x;
    const int lane = tid & 31;
    const int w    = tid >> 5;
    const int b    = bid >> 7;             // 128 CTAs per batch
    const int r    = (bid & 127) << 11;    // chunk start within N*N plane

    // ---- init label tile (2048 ints = 2 int4/thread) + flags
    ((int4*)s_lab)[tid] = make_int4(0, 0, 0, 0);
    ((int4*)s_lab)[tid + 256] = make_int4(0, 0, 0, 0);
    if (tid < 2) s_flags[tid] = 0;
    __syncthreads();

    // ---- scatter this batch's edges (highest e wins, deterministic)
    {
        const int base = b << 10;          // EE = 1024
#pragma unroll
        for (int k = 0; k < 4; k++) {
            int e = tid + (k << 8);
            int2 ij = ((const int2*)ei)[base + e];
            int a   = ea[base + e];
            int pos = ij.x * NND + ij.y - r;
            if ((unsigned)pos < (unsigned)CHUNK)
                atomicMax(&s_lab[pos], (e << 5) | a);
        }
    }

    // ---- mask dtype detection from mask[0..1024) bytes (L2-hot)
    //   u8 bool: nonzero at off%4==1; f32 1.0f: only %4==2,3; i32: only %4==0
    {
        uchar4 mv = ((const uchar4*)mask)[tid];
        if (mv.y) atomicOr(&s_flags[0], 1);
        if (mv.z | mv.w) atomicOr(&s_flags[1], 1);
    }
    __syncthreads();

    const int mode = s_flags[0] ? 0 : (s_flags[1] ? 2 : 1);

    float accs = 0.f, accc = 0.f;          // across both halves

#pragma unroll
    for (int h = 0; h < 2; h++) {
        const int hoff = h << 10;                       // 0 or 1024
        const int p = b * PLANE + r + hoff + tid * 4;   // my global position
        const float* adjb = adj + (size_t)b * CC * PLANE + r + hoff + tid * 4;

        // mask values (uniform branch on mode)
        float v0, v1, v2, v3;
        if (mode == 0) {
            uchar4 mm = ((const uchar4*)mask)[p >> 2];
            v0 = mm.x ? 1.f : 0.f; v1 = mm.y ? 1.f : 0.f;
            v2 = mm.z ? 1.f : 0.f; v3 = mm.w ? 1.f : 0.f;
        } else if (mode == 1) {
            int4 mm = ((const int4*)mask)[p >> 2];
            v0 = mm.x ? 1.f : 0.f; v1 = mm.y ? 1.f : 0.f;
            v2 = mm.z ? 1.f : 0.f; v3 = mm.w ? 1.f : 0.f;
        } else {
            float4 mm = ((const float4*)mask)[p >> 2];
            v0 = (mm.x != 0.f) ? 1.f : 0.f; v1 = (mm.y != 0.f) ? 1.f : 0.f;
            v2 = (mm.z != 0.f) ? 1.f : 0.f; v3 = (mm.w != 0.f) ? 1.f : 0.f;
        }

        // labels for my 4 positions
        int4 lv = ((const int4*)s_lab)[(hoff >> 2) + tid];
        const int lab0 = lv.x & 31, lab1 = lv.y & 31,
                  lab2 = lv.z & 31, lab3 = lv.w & 31;

        // stream 16 classes; consume on the fly; prefetch half 1 during half 0
        float sx = 0.f, sy = 0.f, sz = 0.f, sw = 0.f;
        float p0 = 0.f, p1 = 0.f, p2 = 0.f, p3 = 0.f;
#pragma unroll
        for (int c = 0; c < CC; c++) {
            const float* ap = adjb + (size_t)c * PLANE;
            float4 xc = *(const float4*)ap;
            if (h == 0)
                asm volatile("prefetch.global.L2 [%0];" :: "l"(ap + 1024));
            sx += __expf(xc.x);
            sy += __expf(xc.y);
            sz += __expf(xc.z);
            sw += __expf(xc.w);
            p0 = (c == lab0) ? xc.x : p0;
            p1 = (c == lab1) ? xc.y : p1;
            p2 = (c == lab2) ? xc.z : p2;
            p3 = (c == lab3) ? xc.w : p3;
        }

        accs += v0 * (__logf(sx) - p0) + v1 * (__logf(sy) - p1)
              + v2 * (__logf(sz) - p2) + v3 * (__logf(sw) - p3);
        accc += v0 + v1 + v2 + v3;
    }

    // ---- block reduce (warp shuffle + 8-slot shared)
#pragma unroll
    for (int off = 16; off > 0; off >>= 1) {
        accs += __shfl_down_sync(0xFFFFFFFFu, accs, off);
        accc += __shfl_down_sync(0xFFFFFFFFu, accc, off);
    }
    if (lane == 0) { s_wred[w] = accs; s_wred[8 + w] = accc; }
    __syncthreads();

    if (tid == 0) {
        float bs = 0.f, bc = 0.f;
#pragma unroll
        for (int i = 0; i < 8; i++) { bs += s_wred[i]; bc += s_wred[8 + i]; }
        g_part[bid] = make_float2(bs, bc);
        __threadfence();
        unsigned int old = atomicAdd(&g_done, 1u);
        s_role = ((old & (NCTA - 1)) == (NCTA - 1)) ? 1 : 0;
    }
    __syncthreads();

    // ---- last CTA: reduce 1024 partials; warp w == batch w (128 slots each)
    if (s_role == 1) {
        __threadfence();
        double ds = 0.0, dc = 0.0;
        const int slot0 = w << 7;
#pragma unroll
        for (int k = 0; k < 4; k++) {
            float2 pr = __ldcg(&g_part[slot0 + lane + (k << 5)]);
            ds += (double)pr.x;
            dc += (double)pr.y;
        }
#pragma unroll
        for (int off = 16; off > 0; off >>= 1) {
            ds += __shfl_down_sync(0xFFFFFFFFu, ds, off);
            dc += __shfl_down_sync(0xFFFFFFFFu, dc, off);
        }
        if (lane == 0) {
            if (dc < 1.0) dc = 1.0;
            s_bat[w] = ds / dc;
        }
        __syncthreads();
        if (tid == 0) {
            double acc = 0.0;
#pragma unroll
            for (int i = 0; i < BB; i++) acc += s_bat[i];
            out[0] = (float)(acc / (double)BB);
        }
    }
}

// ---------------------------------------------------------------------------
extern "C" void kernel_launch(void* const* d_in, const int* in_sizes, int n_in,
                              void* d_out, int out_size) {
    const float*         adj  = (const float*)d_in[0];
    const unsigned char* mask = (const unsigned char*)d_in[1];
    const int*           ei   = (const int*)d_in[2];
    const int*           ea   = (const int*)d_in[3];

    fused_kernel<<<NCTA, THREADS>>>(adj, mask, ei, ea, (float*)d_out);
}